// round 13
// baseline (speedup 1.0000x reference)
#include <cuda_runtime.h>
#include <cstdint>

#define WARPS_PER_CTA 2
#define CTA_THREADS   (WARPS_PER_CTA * 32)

// ---- smem layout (u32 units) ----
#define OFF_W2T   0
#define W2T_U32   1152                 // W2 transposed [72][16] fp32 (%4==0)
#define XS_U32    844                  // xs bf16x2[29][29] + pad (to keep %4==0)
#define Z1_U32    3840                 // z1 float2[8][15][16]  (image pair, fp32)
#define WARP_U32  (XS_U32 + Z1_U32)    // 4684 (%4==0)
#define SMEM_U32  (W2T_U32 + WARPS_PER_CTA * WARP_U32)
#define SMEM_BYTES (SMEM_U32 * 4)      // 42080 B -> 5 CTAs/SM (10 warps)

// packed fp32x2 FMA (sm_103a)
__device__ __forceinline__ float2 ffma2(float2 a, float2 b, float2 c) {
    unsigned long long ua = *reinterpret_cast<unsigned long long*>(&a);
    unsigned long long ub = *reinterpret_cast<unsigned long long*>(&b);
    unsigned long long uc = *reinterpret_cast<unsigned long long*>(&c);
    unsigned long long ud;
    asm("fma.rn.f32x2 %0, %1, %2, %3;" : "=l"(ud) : "l"(ua), "l"(ub), "l"(uc));
    return *reinterpret_cast<float2*>(&ud);
}
__device__ __forceinline__ float2 bcast2(float v) { return make_float2(v, v); }

__device__ __forceinline__ uint32_t pack_bf2(float lo, float hi) {
    uint32_t r;
    asm("cvt.rn.satfinite.bf16x2.f32 %0, %1, %2;" : "=r"(r) : "f"(hi), "f"(lo));
    return r;
}
__device__ __forceinline__ float2 unpack_bf2(uint32_t u) {
    float2 f;
    f.x = __uint_as_float(u << 16);
    f.y = __uint_as_float(u & 0xFFFF0000u);
    return f;
}

__device__ __forceinline__ float finish_prob(float z) {
    float sp = fmaxf(z, 0.0f) + log1pf(expf(-fabsf(z)));
    float r  = sp + 0.001f;
    float pr = -expm1f(-r);
    return fminf(fmaxf(pr, 1e-6f), 1.0f - 1e-6f);
}

__global__ __launch_bounds__(CTA_THREADS, 5)
void diffsol_fused_kernel(const float* __restrict__ x,
                          const float* __restrict__ W1,
                          const float* __restrict__ b1,
                          const float* __restrict__ W2,
                          const float* __restrict__ b2,
                          const float* __restrict__ Wfc,
                          const float* __restrict__ bfc,
                          float* __restrict__ out,
                          int npairs) {
    extern __shared__ uint32_t smem[];
    float* sW2t = reinterpret_cast<float*>(smem + OFF_W2T);   // [72][16]

    const int tid = threadIdx.x;
    for (int i = tid; i < 1152; i += CTA_THREADS)
        sW2t[(i % 72) * 16 + (i / 72)] = W2[i];
    __syncthreads();

    const int warp = tid >> 5;
    const int lane = tid & 31;
    const int g = blockIdx.x * WARPS_PER_CTA + warp;   // image-pair id
    if (g >= npairs) return;

    uint32_t* wb  = smem + W2T_U32 + warp * WARP_U32;
    uint32_t* xs  = wb;                                        // [29][29] bf16x2
    float2*   z1f = reinterpret_cast<float2*>(wb + XS_U32);    // [8][15][16] f32 pair

    const float* x0 = x + (size_t)(2 * g) * 784;
    const float* x1 = x0 + 784;

    // ---- stage input pair (R9-proven) ----
    for (int e = lane; e < 784; e += 32) {
        int r = e / 28, c = e - r * 28;
        xs[(r + 1) * 29 + (c + 1)] = pack_bf2(x0[e], x1[e]);
    }
    for (int z = lane; z < 57; z += 32) {
        if (z < 29) xs[z] = 0u;
        else        xs[(z - 28) * 29] = 0u;
    }
    // z1 zero pads: 8ch * (row0: 16, col0 rows 1..14: 14) = 240 float2
    for (int z = lane; z < 240; z += 32) {
        int ch = z / 30, q = z - ch * 30;
        if (q < 16) z1f[ch * 240 + q] = make_float2(0.f, 0.f);
        else        z1f[ch * 240 + (q - 15) * 16] = make_float2(0.f, 0.f);
    }
    __syncwarp();

    // ---- conv1: lane = 4 channels x 16 pixel-lanes (R9-proven), fp32 z1 out ----
    {
        const int chg = lane >> 4;
        const int s1  = lane & 15;
        const int c0  = 4 * chg;
        float w1r[4][9], b1r[4];
        #pragma unroll
        for (int cc = 0; cc < 4; cc++) {
            b1r[cc] = b1[c0 + cc];
            #pragma unroll
            for (int k = 0; k < 9; k++) w1r[cc][k] = W1[(c0 + cc) * 9 + k];
        }

        for (int t = 0; t < 13; t++) {
            int p = s1 + 16 * t;
            int pe = p < 196 ? p : 195;
            int i = pe / 14, j = pe - i * 14;
            const uint32_t* xb = xs + (2 * i) * 29 + 2 * j;
            float2 a[4];
            #pragma unroll
            for (int cc = 0; cc < 4; cc++) a[cc] = bcast2(b1r[cc]);
            #pragma unroll
            for (int di = 0; di < 3; di++)
                #pragma unroll
                for (int dj = 0; dj < 3; dj++) {
                    float2 xv = unpack_bf2(xb[di * 29 + dj]);
                    #pragma unroll
                    for (int cc = 0; cc < 4; cc++)
                        a[cc] = ffma2(xv, bcast2(w1r[cc][di * 3 + dj]), a[cc]);
                }
            if (p < 196) {
                #pragma unroll
                for (int cc = 0; cc < 4; cc++) {
                    z1f[(c0 + cc) * 240 + (i + 1) * 16 + (j + 1)] =
                        make_float2(fmaxf(a[cc].x, 0.f), fmaxf(a[cc].y, 0.f));
                }
            }
        }
    }
    __syncwarp();

    // ---- conv2 (R9-proven structure; taps now fp32 float2, no unpacks) ----
    const int cg = lane >> 3;
    const int ps = lane & 7;
    const int cb = 4 * cg;
    int boff[7];
    #pragma unroll
    for (int t = 0; t < 7; t++) {
        int p = ps + 8 * t;
        int pe = p < 49 ? p : 48;
        int i = pe / 7, j = pe - i * 7;
        boff[t] = (2 * i) * 16 + 2 * j;   // even float2 index -> 16B aligned base
    }

    float2 acc[4][7];
    #pragma unroll
    for (int cc = 0; cc < 4; cc++) {
        float bb = b2[cb + cc];
        #pragma unroll
        for (int t = 0; t < 7; t++) acc[cc][t] = bcast2(bb);
    }

    const float4* W2T4 = reinterpret_cast<const float4*>(sW2t);
    #pragma unroll 1
    for (int ci = 0; ci < 8; ci++) {
        const float2* zb = z1f + ci * 240;
        const int wk = ci * 9;
        #pragma unroll
        for (int di = 0; di < 3; di++) {
            float4 wd0 = W2T4[(wk + di * 3 + 0) * 4 + cg];
            float4 wd1 = W2T4[(wk + di * 3 + 1) * 4 + cg];
            float4 wd2 = W2T4[(wk + di * 3 + 2) * 4 + cg];
            float w0[4] = {wd0.x, wd0.y, wd0.z, wd0.w};
            float w1[4] = {wd1.x, wd1.y, wd1.z, wd1.w};
            float w2[4] = {wd2.x, wd2.y, wd2.z, wd2.w};
            #pragma unroll
            for (int t = 0; t < 7; t++) {
                const float2* zp = zb + boff[t] + di * 16;
                float4 e01 = *reinterpret_cast<const float4*>(zp);  // taps dj=0,1
                float2 z2v = zp[2];                                  // tap dj=2
                float2 z0  = make_float2(e01.x, e01.y);
                float2 z1v = make_float2(e01.z, e01.w);
                #pragma unroll
                for (int cc = 0; cc < 4; cc++) {
                    acc[cc][t] = ffma2(z0,  bcast2(w0[cc]), acc[cc][t]);
                    acc[cc][t] = ffma2(z1v, bcast2(w1[cc]), acc[cc][t]);
                    acc[cc][t] = ffma2(z2v, bcast2(w2[cc]), acc[cc][t]);
                }
            }
        }
    }

    // ---- FC: relu(z2) . Wfc (R9-proven), warp reduce ----
    float2 part = make_float2(0.f, 0.f);
    #pragma unroll
    for (int cc = 0; cc < 4; cc++)
        #pragma unroll
        for (int t = 0; t < 7; t++) {
            int p = ps + 8 * t;
            if (p < 49) {
                float wf = Wfc[(cb + cc) * 49 + p];
                float2 rz = make_float2(fmaxf(acc[cc][t].x, 0.f), fmaxf(acc[cc][t].y, 0.f));
                part = ffma2(rz, bcast2(wf), part);
            }
        }

    #pragma unroll
    for (int off = 16; off; off >>= 1) {
        part.x += __shfl_xor_sync(0xffffffffu, part.x, off);
        part.y += __shfl_xor_sync(0xffffffffu, part.y, off);
    }

    if (lane == 0) {
        float bb = bfc[0];
        out[2 * g]     = finish_prob(part.x + bb);
        out[2 * g + 1] = finish_prob(part.y + bb);
    }
}

extern "C" void kernel_launch(void* const* d_in, const int* in_sizes, int n_in,
                              void* d_out, int out_size) {
    const float* x   = (const float*)d_in[0];
    const float* W1  = (const float*)d_in[1];
    const float* b1  = (const float*)d_in[2];
    const float* W2  = (const float*)d_in[3];
    const float* b2  = (const float*)d_in[4];
    const float* Wfc = (const float*)d_in[5];
    const float* bfc = (const float*)d_in[6];
    float* out = (float*)d_out;

    int nimg = in_sizes[0] / 784;
    int npairs = nimg / 2;
    int ctas = (npairs + WARPS_PER_CTA - 1) / WARPS_PER_CTA;

    cudaFuncSetAttribute(diffsol_fused_kernel,
                         cudaFuncAttributeMaxDynamicSharedMemorySize, SMEM_BYTES);
    diffsol_fused_kernel<<<ctas, CTA_THREADS, SMEM_BYTES>>>(
        x, W1, b1, W2, b2, Wfc, bfc, out, npairs);
}

// round 14
// speedup vs baseline: 1.5334x; 1.5334x over previous
#include <cuda_runtime.h>
#include <cstdint>

#define WARPS_PER_CTA 4
#define CTA_THREADS   (WARPS_PER_CTA * 32)

// ---- smem layout (u32 units): per-warp activation buffers only ----
#define XS_U32    842                  // xs bf16x2[29][29] + pad
#define Z1_U32    1920                 // z1 bf16x2[8][15][16]
#define WARP_U32  (XS_U32 + Z1_U32)    // 2762
#define SMEM_U32  (WARPS_PER_CTA * WARP_U32)
#define SMEM_BYTES (SMEM_U32 * 4)      // 44192 B -> 5 CTAs/SM (20 warps)

// gmem scratch: W2 transposed [72 k][16 och], written by init kernel
__device__ __align__(16) float g_W2T[72 * 16];

__device__ __forceinline__ float2 ffma2(float2 a, float2 b, float2 c) {
    unsigned long long ua = *reinterpret_cast<unsigned long long*>(&a);
    unsigned long long ub = *reinterpret_cast<unsigned long long*>(&b);
    unsigned long long uc = *reinterpret_cast<unsigned long long*>(&c);
    unsigned long long ud;
    asm("fma.rn.f32x2 %0, %1, %2, %3;" : "=l"(ud) : "l"(ua), "l"(ub), "l"(uc));
    return *reinterpret_cast<float2*>(&ud);
}
__device__ __forceinline__ float2 bcast2(float v) { return make_float2(v, v); }

__device__ __forceinline__ uint32_t pack_bf2(float lo, float hi) {
    uint32_t r;
    asm("cvt.rn.satfinite.bf16x2.f32 %0, %1, %2;" : "=r"(r) : "f"(hi), "f"(lo));
    return r;
}
__device__ __forceinline__ float2 unpack_bf2(uint32_t u) {
    float2 f;
    f.x = __uint_as_float(u << 16);
    f.y = __uint_as_float(u & 0xFFFF0000u);
    return f;
}

__device__ __forceinline__ float finish_prob(float z) {
    float sp = fmaxf(z, 0.0f) + log1pf(expf(-fabsf(z)));
    float r  = sp + 0.001f;
    float pr = -expm1f(-r);
    return fminf(fmaxf(pr, 1e-6f), 1.0f - 1e-6f);
}

// ---- init: transpose W2 [16][72] -> g_W2T [72][16] ----
__global__ void init_weights_kernel(const float* __restrict__ W2) {
    int i = blockIdx.x * blockDim.x + threadIdx.x;
    if (i < 1152) g_W2T[(i % 72) * 16 + (i / 72)] = W2[i];
}

__global__ __launch_bounds__(CTA_THREADS, 5)
void diffsol_fused_kernel(const float* __restrict__ x,
                          const float* __restrict__ W1,
                          const float* __restrict__ b1,
                          const float* __restrict__ b2,
                          const float* __restrict__ Wfc,
                          const float* __restrict__ bfc,
                          float* __restrict__ out,
                          int npairs) {
    extern __shared__ uint32_t smem[];

    const int tid  = threadIdx.x;
    const int warp = tid >> 5;
    const int lane = tid & 31;
    const int g = blockIdx.x * WARPS_PER_CTA + warp;   // image-pair id
    if (g >= npairs) return;

    uint32_t* wb  = smem + warp * WARP_U32;
    uint32_t* xs  = wb;             // [29][29] bf16x2, zero-pad top/left
    uint32_t* z1s = wb + XS_U32;    // [8][15][16] bf16x2, zero-pad row0/col0

    const float* x0 = x + (size_t)(2 * g) * 784;
    const float* x1 = x0 + 784;

    // ---- stage input pair (R9-proven) ----
    for (int e = lane; e < 784; e += 32) {
        int r = e / 28, c = e - r * 28;
        xs[(r + 1) * 29 + (c + 1)] = pack_bf2(x0[e], x1[e]);
    }
    for (int z = lane; z < 57; z += 32) {
        if (z < 29) xs[z] = 0u;
        else        xs[(z - 28) * 29] = 0u;
    }
    for (int z = lane; z < 240; z += 32) {     // z1 pads: 8ch * (16 + 14)
        int ch = z / 30, q = z - ch * 30;
        if (q < 16) z1s[ch * 240 + q] = 0u;
        else        z1s[ch * 240 + (q - 15) * 16] = 0u;
    }
    __syncwarp();

    // ---- conv1: lane = 4 channels x 16 pixel-lanes (R9-proven) ----
    {
        const int chg = lane >> 4;
        const int s1  = lane & 15;
        const int c0  = 4 * chg;
        float w1r[4][9], b1r[4];
        #pragma unroll
        for (int cc = 0; cc < 4; cc++) {
            b1r[cc] = b1[c0 + cc];
            #pragma unroll
            for (int k = 0; k < 9; k++) w1r[cc][k] = W1[(c0 + cc) * 9 + k];
        }

        for (int t = 0; t < 13; t++) {
            int p = s1 + 16 * t;
            int pe = p < 196 ? p : 195;
            int i = pe / 14, j = pe - i * 14;
            const uint32_t* xb = xs + (2 * i) * 29 + 2 * j;
            float2 a[4];
            #pragma unroll
            for (int cc = 0; cc < 4; cc++) a[cc] = bcast2(b1r[cc]);
            #pragma unroll
            for (int di = 0; di < 3; di++)
                #pragma unroll
                for (int dj = 0; dj < 3; dj++) {
                    float2 xv = unpack_bf2(xb[di * 29 + dj]);
                    #pragma unroll
                    for (int cc = 0; cc < 4; cc++)
                        a[cc] = ffma2(xv, bcast2(w1r[cc][di * 3 + dj]), a[cc]);
                }
            if (p < 196) {
                #pragma unroll
                for (int cc = 0; cc < 4; cc++) {
                    float lo = fmaxf(a[cc].x, 0.f);
                    float hi = fmaxf(a[cc].y, 0.f);
                    z1s[(c0 + cc) * 240 + (i + 1) * 16 + (j + 1)] = pack_bf2(lo, hi);
                }
            }
        }
    }
    __syncwarp();

    // ---- conv2 (R9-proven; weight quads from gmem-L1 transposed scratch) ----
    const int cg = lane >> 3;
    const int ps = lane & 7;
    const int cb = 4 * cg;
    int boff[7];
    #pragma unroll
    for (int t = 0; t < 7; t++) {
        int p = ps + 8 * t;
        int pe = p < 49 ? p : 48;
        int i = pe / 7, j = pe - i * 7;
        boff[t] = (2 * i) * 16 + 2 * j;
    }

    float2 acc[4][7];
    #pragma unroll
    for (int cc = 0; cc < 4; cc++) {
        float bb = b2[cb + cc];
        #pragma unroll
        for (int t = 0; t < 7; t++) acc[cc][t] = bcast2(bb);
    }

    const float4* W2T4 = reinterpret_cast<const float4*>(g_W2T);
    #pragma unroll 1
    for (int ci = 0; ci < 8; ci++) {
        const uint32_t* zb = z1s + ci * 240;
        const int wk = ci * 9;
        #pragma unroll
        for (int di = 0; di < 3; di++) {
            float4 wd0 = W2T4[(wk + di * 3 + 0) * 4 + cg];
            float4 wd1 = W2T4[(wk + di * 3 + 1) * 4 + cg];
            float4 wd2 = W2T4[(wk + di * 3 + 2) * 4 + cg];
            float w0[4] = {wd0.x, wd0.y, wd0.z, wd0.w};
            float w1[4] = {wd1.x, wd1.y, wd1.z, wd1.w};
            float w2[4] = {wd2.x, wd2.y, wd2.z, wd2.w};
            #pragma unroll
            for (int t = 0; t < 7; t++) {
                const uint32_t* zp = zb + boff[t] + di * 16;
                uint2 pr = *reinterpret_cast<const uint2*>(zp);
                uint32_t p2 = zp[2];
                float2 z0  = unpack_bf2(pr.x);
                float2 z1v = unpack_bf2(pr.y);
                float2 z2v = unpack_bf2(p2);
                #pragma unroll
                for (int cc = 0; cc < 4; cc++) {
                    acc[cc][t] = ffma2(z0,  bcast2(w0[cc]), acc[cc][t]);
                    acc[cc][t] = ffma2(z1v, bcast2(w1[cc]), acc[cc][t]);
                    acc[cc][t] = ffma2(z2v, bcast2(w2[cc]), acc[cc][t]);
                }
            }
        }
    }

    // ---- FC: relu(z2) . Wfc (gmem/L1), warp reduce (R9-proven) ----
    float2 part = make_float2(0.f, 0.f);
    #pragma unroll
    for (int cc = 0; cc < 4; cc++)
        #pragma unroll
        for (int t = 0; t < 7; t++) {
            int p = ps + 8 * t;
            if (p < 49) {
                float wf = Wfc[(cb + cc) * 49 + p];
                float2 rz = make_float2(fmaxf(acc[cc][t].x, 0.f), fmaxf(acc[cc][t].y, 0.f));
                part = ffma2(rz, bcast2(wf), part);
            }
        }

    #pragma unroll
    for (int off = 16; off; off >>= 1) {
        part.x += __shfl_xor_sync(0xffffffffu, part.x, off);
        part.y += __shfl_xor_sync(0xffffffffu, part.y, off);
    }

    if (lane == 0) {
        float bb = bfc[0];
        out[2 * g]     = finish_prob(part.x + bb);
        out[2 * g + 1] = finish_prob(part.y + bb);
    }
}

extern "C" void kernel_launch(void* const* d_in, const int* in_sizes, int n_in,
                              void* d_out, int out_size) {
    const float* x   = (const float*)d_in[0];
    const float* W1  = (const float*)d_in[1];
    const float* b1  = (const float*)d_in[2];
    const float* W2  = (const float*)d_in[3];
    const float* b2  = (const float*)d_in[4];
    const float* Wfc = (const float*)d_in[5];
    const float* bfc = (const float*)d_in[6];
    float* out = (float*)d_out;

    int nimg = in_sizes[0] / 784;
    int npairs = nimg / 2;
    int ctas = (npairs + WARPS_PER_CTA - 1) / WARPS_PER_CTA;

    init_weights_kernel<<<9, 128>>>(W2);

    cudaFuncSetAttribute(diffsol_fused_kernel,
                         cudaFuncAttributeMaxDynamicSharedMemorySize, SMEM_BYTES);
    diffsol_fused_kernel<<<ctas, CTA_THREADS, SMEM_BYTES>>>(
        x, W1, b1, b2, Wfc, bfc, out, npairs);
}